// round 2
// baseline (speedup 1.0000x reference)
#include <cuda_runtime.h>
#include <cuda_bf16.h>
#include <cstdint>

// Problem constants
#define BATCH 4
#define SEQ   4096
#define QD    1024
#define HEADS 8
#define DH    64
#define HID   512          // HEADS*DH
#define MROWS (BATCH*SEQ)  // 16384
#define QSCALE 0.125f      // DH^-0.5

// Scratch layout (floats)
#define Q_OFF   0u
#define K_OFF   8388608u            // 16384*512
#define V_OFF   16777216u
#define KM_OFF  25165824u           // [4*512] column max of k
#define KSI_OFF 25167872u           // [4*512] 1/sum(exp)
#define CTX_OFF 25169920u           // partial ctx: [8 chunks][4][8][64][64] = 1048576
#define W2_OFF  26218496u           // [4][512][1024] = 2097152
#define SCRATCH_TOTAL 30412800u     // ~121.6 MB

__device__ float g_scratch[SCRATCH_TOTAL];

// ---------------------------------------------------------------------------
// Tiled SGEMM: C[M,N] = A[M,K] @ B[K,N] (+bias), row-major, fp32.
// 128x128 tile, BK=8, 256 threads, 8x8 microtile (4+4 split for vector smem).
// blockIdx.z batches with the given strides.
// ---------------------------------------------------------------------------
__global__ __launch_bounds__(256, 2)
void sgemm128(const float* __restrict__ A, const float* __restrict__ Bm,
              float* __restrict__ C, const float* __restrict__ bias,
              int M, int N, int K,
              long long sA, long long sB, long long sC)
{
    A  += (long long)blockIdx.z * sA;
    Bm += (long long)blockIdx.z * sB;
    C  += (long long)blockIdx.z * sC;

    __shared__ float As[8][128];   // transposed A tile
    __shared__ float Bs[8][128];

    const int tid  = threadIdx.x;
    const int cRow = blockIdx.y * 128;
    const int cCol = blockIdx.x * 128;

    const int aRow = tid >> 1;          // 0..127
    const int aCol = (tid & 1) * 4;     // 0 or 4
    const int bRow = tid >> 5;          // 0..7
    const int bCol = (tid & 31) * 4;    // 0..124

    const int tx = tid & 15;
    const int ty = tid >> 4;

    const float* Ap = A  + (size_t)(cRow + aRow) * K + aCol;
    const float* Bp = Bm + (size_t)bRow * N + cCol + bCol;

    float acc[8][8];
    #pragma unroll
    for (int i = 0; i < 8; i++)
        #pragma unroll
        for (int j = 0; j < 8; j++) acc[i][j] = 0.f;

    for (int k0 = 0; k0 < K; k0 += 8) {
        float4 av = *reinterpret_cast<const float4*>(Ap + k0);
        As[aCol + 0][aRow] = av.x;
        As[aCol + 1][aRow] = av.y;
        As[aCol + 2][aRow] = av.z;
        As[aCol + 3][aRow] = av.w;
        *reinterpret_cast<float4*>(&Bs[bRow][bCol]) =
            *reinterpret_cast<const float4*>(Bp + (size_t)k0 * N);
        __syncthreads();

        #pragma unroll
        for (int kk = 0; kk < 8; kk++) {
            float4 a0 = *reinterpret_cast<float4*>(&As[kk][ty * 4]);
            float4 a1 = *reinterpret_cast<float4*>(&As[kk][64 + ty * 4]);
            float4 b0 = *reinterpret_cast<float4*>(&Bs[kk][tx * 4]);
            float4 b1 = *reinterpret_cast<float4*>(&Bs[kk][64 + tx * 4]);
            float ra[8] = {a0.x, a0.y, a0.z, a0.w, a1.x, a1.y, a1.z, a1.w};
            float rb[8] = {b0.x, b0.y, b0.z, b0.w, b1.x, b1.y, b1.z, b1.w};
            #pragma unroll
            for (int i = 0; i < 8; i++)
                #pragma unroll
                for (int j = 0; j < 8; j++)
                    acc[i][j] += ra[i] * rb[j];
        }
        __syncthreads();
    }

    float4 bv0 = make_float4(0.f, 0.f, 0.f, 0.f);
    float4 bv1 = make_float4(0.f, 0.f, 0.f, 0.f);
    if (bias) {
        bv0 = *reinterpret_cast<const float4*>(&bias[cCol + tx * 4]);
        bv1 = *reinterpret_cast<const float4*>(&bias[cCol + 64 + tx * 4]);
    }

    #pragma unroll
    for (int i = 0; i < 8; i++) {
        int r = cRow + ((i < 4) ? (ty * 4 + i) : (64 + ty * 4 + i - 4));
        float4 o0 = make_float4(acc[i][0] + bv0.x, acc[i][1] + bv0.y,
                                acc[i][2] + bv0.z, acc[i][3] + bv0.w);
        float4 o1 = make_float4(acc[i][4] + bv1.x, acc[i][5] + bv1.y,
                                acc[i][6] + bv1.z, acc[i][7] + bv1.w);
        *reinterpret_cast<float4*>(&C[(size_t)r * N + cCol + tx * 4])      = o0;
        *reinterpret_cast<float4*>(&C[(size_t)r * N + cCol + 64 + tx * 4]) = o1;
    }
}

// ---------------------------------------------------------------------------
// q softmax over contiguous 64-element head groups, *QSCALE, in place.
// One warp per group, 2 elems per lane (float2).
// ---------------------------------------------------------------------------
__global__ void q_softmax_kernel(float* __restrict__ q)
{
    int w    = threadIdx.x >> 5;
    int lane = threadIdx.x & 31;
    size_t g = (size_t)blockIdx.x * 8 + w;        // group index, 131072 total
    float2* p = reinterpret_cast<float2*>(q) + g * 32 + lane;
    float2 v = *p;
    float m = fmaxf(v.x, v.y);
    #pragma unroll
    for (int o = 16; o > 0; o >>= 1)
        m = fmaxf(m, __shfl_xor_sync(0xffffffffu, m, o));
    float ex = __expf(v.x - m);
    float ey = __expf(v.y - m);
    float s = ex + ey;
    #pragma unroll
    for (int o = 16; o > 0; o >>= 1)
        s += __shfl_xor_sync(0xffffffffu, s, o);
    float sc = QSCALE / s;
    *p = make_float2(ex * sc, ey * sc);
}

// ---------------------------------------------------------------------------
// k column stats over n (per (b, c) with c = h*64+d): max and 1/sum(exp).
// Grid (8 col-tiles of 64, batch), block (64, 4).
// ---------------------------------------------------------------------------
__global__ void k_stats_kernel(const float* __restrict__ k,
                               float* __restrict__ km, float* __restrict__ ksi)
{
    int b  = blockIdx.y;
    int c  = blockIdx.x * 64 + threadIdx.x;
    int ty = threadIdx.y;
    const float* base = k + (size_t)b * SEQ * HID + c;

    __shared__ float red[4][64];

    float m = -1e30f;
    for (int n = ty; n < SEQ; n += 4)
        m = fmaxf(m, base[(size_t)n * HID]);
    red[ty][threadIdx.x] = m;
    __syncthreads();
    m = fmaxf(fmaxf(red[0][threadIdx.x], red[1][threadIdx.x]),
              fmaxf(red[2][threadIdx.x], red[3][threadIdx.x]));
    __syncthreads();

    float s = 0.f;
    for (int n = ty; n < SEQ; n += 4)
        s += __expf(base[(size_t)n * HID] - m);
    red[ty][threadIdx.x] = s;
    __syncthreads();
    if (ty == 0) {
        float st = red[0][threadIdx.x] + red[1][threadIdx.x] +
                   red[2][threadIdx.x] + red[3][threadIdx.x];
        km [b * HID + c] = m;
        ksi[b * HID + c] = 1.0f / st;
    }
}

// ---------------------------------------------------------------------------
// Partial context: for each (chunk, b, h) accumulate over 512 tokens:
//   ctxp[chunk][b][h][d][e] = sum_n softk[n][d] * v[n][e]
// Block (16,16), each thread 4x4 of the 64x64 output. Deterministic (no atomics).
// ---------------------------------------------------------------------------
__global__ __launch_bounds__(256, 4)
void context_kernel(const float* __restrict__ k, const float* __restrict__ v,
                    const float* __restrict__ km, const float* __restrict__ ksi,
                    float* __restrict__ ctxp)
{
    int chunk = blockIdx.x;   // 8
    int h     = blockIdx.y;   // 8
    int b     = blockIdx.z;   // 4
    int tx = threadIdx.x, ty = threadIdx.y;
    int tid = ty * 16 + tx;

    __shared__ float Ks[32][64];
    __shared__ float Vs[32][64];
    __shared__ float ms[64], si[64];

    if (tid < 64) {
        ms[tid] = km [b * HID + h * DH + tid];
        si[tid] = ksi[b * HID + h * DH + tid];
    }
    __syncthreads();

    const float* kb = k + (size_t)b * SEQ * HID + h * DH;
    const float* vb = v + (size_t)b * SEQ * HID + h * DH;
    int n0 = chunk * 512;

    float acc[4][4];
    #pragma unroll
    for (int r = 0; r < 4; r++)
        #pragma unroll
        for (int c = 0; c < 4; c++) acc[r][c] = 0.f;

    for (int nn = 0; nn < 512; nn += 32) {
        int ii = tid >> 3;            // 0..31
        int d0 = (tid & 7) * 8;       // 0..56
        size_t off = (size_t)(n0 + nn + ii) * HID + d0;
        float4 k0v = *reinterpret_cast<const float4*>(kb + off);
        float4 k1v = *reinterpret_cast<const float4*>(kb + off + 4);
        float4 v0v = *reinterpret_cast<const float4*>(vb + off);
        float4 v1v = *reinterpret_cast<const float4*>(vb + off + 4);
        Ks[ii][d0 + 0] = __expf(k0v.x - ms[d0 + 0]) * si[d0 + 0];
        Ks[ii][d0 + 1] = __expf(k0v.y - ms[d0 + 1]) * si[d0 + 1];
        Ks[ii][d0 + 2] = __expf(k0v.z - ms[d0 + 2]) * si[d0 + 2];
        Ks[ii][d0 + 3] = __expf(k0v.w - ms[d0 + 3]) * si[d0 + 3];
        Ks[ii][d0 + 4] = __expf(k1v.x - ms[d0 + 4]) * si[d0 + 4];
        Ks[ii][d0 + 5] = __expf(k1v.y - ms[d0 + 5]) * si[d0 + 5];
        Ks[ii][d0 + 6] = __expf(k1v.z - ms[d0 + 6]) * si[d0 + 6];
        Ks[ii][d0 + 7] = __expf(k1v.w - ms[d0 + 7]) * si[d0 + 7];
        *reinterpret_cast<float4*>(&Vs[ii][d0])     = v0v;
        *reinterpret_cast<float4*>(&Vs[ii][d0 + 4]) = v1v;
        __syncthreads();

        #pragma unroll
        for (int i = 0; i < 32; i++) {
            float4 rav = *reinterpret_cast<float4*>(&Ks[i][ty * 4]);
            float4 rbv = *reinterpret_cast<float4*>(&Vs[i][tx * 4]);
            float ra[4] = {rav.x, rav.y, rav.z, rav.w};
            float rb[4] = {rbv.x, rbv.y, rbv.z, rbv.w};
            #pragma unroll
            for (int r = 0; r < 4; r++)
                #pragma unroll
                for (int c = 0; c < 4; c++)
                    acc[r][c] += ra[r] * rb[c];
        }
        __syncthreads();
    }

    float* dst = ctxp + ((((size_t)chunk * BATCH + b) * HEADS + h) * DH) * DH;
    #pragma unroll
    for (int r = 0; r < 4; r++) {
        #pragma unroll
        for (int c = 0; c < 4; c++)
            dst[(ty * 4 + r) * DH + tx * 4 + c] = acc[r][c];
    }
}

// ---------------------------------------------------------------------------
// W2[b][h*64+d][j] = sum_e ctx[b][h][d][e] * Wo[h*64+e][j]
// ctx summed over the 8 partial chunks on load. Grid (8 jtiles, 8 h, 4 b),
// block (32, 8): each thread 8 rows x 4 cols of the 64x128 out tile.
// ---------------------------------------------------------------------------
__global__ void w2_kernel(const float* __restrict__ ctxp,
                          const float* __restrict__ Wo,
                          float* __restrict__ w2)
{
    int jt = blockIdx.x;  // j0 = jt*128
    int h  = blockIdx.y;
    int b  = blockIdx.z;
    int tx = threadIdx.x;         // 32
    int ty = threadIdx.y;         // 8
    int tid = ty * 32 + tx;

    __shared__ float Cs[64][64];     // 16 KB
    __shared__ float Ws[64][128];    // 32 KB

    // reduce 8 chunks of ctx partials
    for (int l = tid; l < 4096; l += 256) {
        size_t base = ((size_t)b * HEADS + h) * 4096 + l;
        float s = 0.f;
        #pragma unroll
        for (int ch = 0; ch < 8; ch++)
            s += ctxp[base + (size_t)ch * (BATCH * HEADS * 4096)];
        Cs[l >> 6][l & 63] = s;
    }
    // load Wo tile [64 e][128 j] : 2048 float4s = 32 float4 per row
    for (int l = tid; l < 2048; l += 256) {
        int e  = l >> 5;              // 0..63  (FIXED: was l>>4 -> OOB)
        int j4 = (l & 31) * 4;        // 0..124 (FIXED: was (l&15)*4)
        *reinterpret_cast<float4*>(&Ws[e][j4]) =
            *reinterpret_cast<const float4*>(&Wo[(size_t)(h * DH + e) * QD + jt * 128 + j4]);
    }
    __syncthreads();

    float acc[8][4];
    #pragma unroll
    for (int r = 0; r < 8; r++)
        #pragma unroll
        for (int c = 0; c < 4; c++) acc[r][c] = 0.f;

    #pragma unroll
    for (int e = 0; e < 64; e++) {
        float4 rb = *reinterpret_cast<float4*>(&Ws[e][tx * 4]);
        #pragma unroll
        for (int r = 0; r < 8; r++) {
            float ra = Cs[ty * 8 + r][e];
            acc[r][0] += ra * rb.x;
            acc[r][1] += ra * rb.y;
            acc[r][2] += ra * rb.z;
            acc[r][3] += ra * rb.w;
        }
    }

    #pragma unroll
    for (int r = 0; r < 8; r++) {
        int row = h * DH + ty * 8 + r;
        *reinterpret_cast<float4*>(&w2[((size_t)b * HID + row) * QD + jt * 128 + tx * 4]) =
            make_float4(acc[r][0], acc[r][1], acc[r][2], acc[r][3]);
    }
}

// ---------------------------------------------------------------------------
extern "C" void kernel_launch(void* const* d_in, const int* in_sizes, int n_in,
                              void* d_out, int out_size)
{
    const float* x  = (const float*)d_in[0];
    const float* Wq = (const float*)d_in[1];
    const float* Wk = (const float*)d_in[2];
    const float* Wv = (const float*)d_in[3];
    const float* Wo = (const float*)d_in[4];
    const float* bo = (const float*)d_in[5];
    float* out = (float*)d_out;

    float* scratch = nullptr;
    cudaGetSymbolAddress((void**)&scratch, g_scratch);
    float* q    = scratch + Q_OFF;
    float* k    = scratch + K_OFF;
    float* v    = scratch + V_OFF;
    float* km   = scratch + KM_OFF;
    float* ksi  = scratch + KSI_OFF;
    float* ctxp = scratch + CTX_OFF;
    float* w2   = scratch + W2_OFF;

    // 1) QKV projections: [16384,1024] @ [1024,512]
    dim3 gProj(HID / 128, MROWS / 128, 1);
    sgemm128<<<gProj, 256>>>(x, Wq, q, nullptr, MROWS, HID, QD, 0, 0, 0);
    sgemm128<<<gProj, 256>>>(x, Wk, k, nullptr, MROWS, HID, QD, 0, 0, 0);
    sgemm128<<<gProj, 256>>>(x, Wv, v, nullptr, MROWS, HID, QD, 0, 0, 0);

    // 2) q softmax over d-groups (in place)
    q_softmax_kernel<<<MROWS, 256>>>(q);

    // 3) k column stats
    k_stats_kernel<<<dim3(HID / 64, BATCH), dim3(64, 4)>>>(k, km, ksi);

    // 4) partial context (8 chunks of 512 tokens)
    context_kernel<<<dim3(8, HEADS, BATCH), dim3(16, 16)>>>(k, v, km, ksi, ctxp);

    // 5) fold context into per-batch effective weight W2 = blockdiag(ctx) @ Wo
    w2_kernel<<<dim3(8, HEADS, BATCH), dim3(32, 8)>>>(ctxp, Wo, w2);

    // 6) final batched GEMM: out[b] = q_soft[b] @ W2[b] + bo
    dim3 gOut(QD / 128, SEQ / 128, BATCH);
    sgemm128<<<gOut, 256>>>(q, w2, out, bo,
                            SEQ, QD, HID,
                            (long long)SEQ * HID,
                            (long long)HID * QD,
                            (long long)SEQ * QD);
}

// round 4
// speedup vs baseline: 2.4076x; 2.4076x over previous
#include <cuda_runtime.h>
#include <cuda_bf16.h>
#include <cstdint>

// ---------------- problem constants ----------------
#define BATCH 4
#define SEQ   4096
#define QD    1024
#define HEADS 8
#define DH    64
#define HID   512
#define MROWS (BATCH*SEQ)     // 16384
#define NTOT  1536            // q|k|v packed columns
#define QSCALE 0.125f

// ---------------- scratch layout (bytes) ----------------
#define SC_C      0ull                    // qkv fp32 [16384][1536]
#define SC_XHI    100663296ull           // x hi bf16 [16384][1024]
#define SC_XLO    134217728ull
#define SC_WTHI   167772160ull           // W^T hi bf16 [1536][1024]
#define SC_WTLO   170917888ull
#define SC_QHI    174063616ull           // q_soft hi bf16 [16384][512]
#define SC_QLO    190840832ull
#define SC_KM     207618048ull           // [4][512] fp32
#define SC_KSI    207626240ull
#define SC_CTXP   207634432ull           // [8][4][8][64][64] fp32
#define SC_W2THI  211828736ull           // W2^T hi bf16 [4][1024][512]
#define SC_W2TLO  216023040ull
#define SC_TOTAL  220217344ull

__device__ __align__(1024) unsigned char g_scratch[SC_TOTAL];

// ---------------- PTX helpers (base-PTX only: mma.sync / ldmatrix / cp.async) --
__device__ __forceinline__ uint32_t smem_u32(const void* p) {
    uint32_t a;
    asm("{ .reg .u64 t; cvta.to.shared.u64 t, %1; cvt.u32.u64 %0, t; }" : "=r"(a) : "l"(p));
    return a;
}
__device__ __forceinline__ void cp_async16(uint32_t dst, const void* src) {
    asm volatile("cp.async.cg.shared.global [%0], [%1], 16;" :: "r"(dst), "l"(src) : "memory");
}
__device__ __forceinline__ void cp_commit() {
    asm volatile("cp.async.commit_group;" ::: "memory");
}
__device__ __forceinline__ void ldsm_x4(uint32_t& r0, uint32_t& r1, uint32_t& r2, uint32_t& r3,
                                        uint32_t addr) {
    asm volatile("ldmatrix.sync.aligned.m8n8.x4.shared.b16 {%0,%1,%2,%3}, [%4];"
                 : "=r"(r0), "=r"(r1), "=r"(r2), "=r"(r3) : "r"(addr));
}
__device__ __forceinline__ void mma_bf16(float* d, const uint32_t* a, const uint32_t* b) {
    asm volatile(
        "mma.sync.aligned.m16n8k16.row.col.f32.bf16.bf16.f32 "
        "{%0,%1,%2,%3}, {%4,%5,%6,%7}, {%8,%9}, {%0,%1,%2,%3};"
        : "+f"(d[0]), "+f"(d[1]), "+f"(d[2]), "+f"(d[3])
        : "r"(a[0]), "r"(a[1]), "r"(a[2]), "r"(a[3]), "r"(b[0]), "r"(b[1]));
}

// smem stage layout: AH 0 / AL 16K / BH 32K / BL 48K ; 64KB per stage, 2 stages
#define STG_AL 16384
#define STG_BH 32768
#define STG_BL 49152
#define STG_SZ 65536
#define GSM_TOTAL (2*STG_SZ)

// ---------------------------------------------------------------------------
// bf16 3-term split GEMM via mma.sync:
//   C[m][n] = sum_k A[m][k]*B[n][k] (+bias[n])
// CTA tile 128(M) x 128(N), BK=64, 256 threads (8 warps, 2x4; warp = 64x32).
// grid: (N/128, M/128, batch)
// ---------------------------------------------------------------------------
__global__ __launch_bounds__(256, 1)
void gemm_mma(const __nv_bfloat16* __restrict__ Ahi, const __nv_bfloat16* __restrict__ Alo,
              const __nv_bfloat16* __restrict__ Bhi, const __nv_bfloat16* __restrict__ Blo,
              float* __restrict__ C, const float* __restrict__ bias,
              int K, int ldc,
              long long sA, long long sB, long long sC)
{
    extern __shared__ char smem[];
    const uint32_t sb = smem_u32(smem);
    const int tid  = threadIdx.x;
    const int wid  = tid >> 5;
    const int lane = tid & 31;
    const int wm = wid >> 2;           // 0..1
    const int wn = wid & 3;            // 0..3

    const int n0 = blockIdx.x * 128;
    const int m0 = blockIdx.y * 128;
    const long long bz = blockIdx.z;
    const __nv_bfloat16* aH = Ahi + bz * sA + (size_t)m0 * K;
    const __nv_bfloat16* aL = Alo + bz * sA + (size_t)m0 * K;
    const __nv_bfloat16* bH = Bhi + bz * sB + (size_t)n0 * K;
    const __nv_bfloat16* bL = Blo + bz * sB + (size_t)n0 * K;
    float* Cb = C + bz * sC;

    const int NC = K >> 6;

    float acc[4][4][4];
    #pragma unroll
    for (int i = 0; i < 4; i++)
        #pragma unroll
        for (int j = 0; j < 4; j++)
            #pragma unroll
            for (int l = 0; l < 4; l++) acc[i][j][l] = 0.f;

    const int g  = lane >> 3;     // ldmatrix address group 0..3
    const int lr = lane & 7;

#define ISSUE(cc, ss) do {                                                       \
    const int ck_ = (cc) << 6;                                                   \
    const uint32_t bs_ = sb + (ss) * STG_SZ;                                     \
    _Pragma("unroll")                                                            \
    for (int j_ = 0; j_ < 4; j_++) {                                             \
        int idx_ = tid + j_ * 256;                                               \
        int r_ = idx_ >> 3, c16_ = idx_ & 7;                                     \
        uint32_t d_ = bs_ + (uint32_t)(r_ * 128 + ((c16_ ^ (r_ & 7)) << 4));     \
        const size_t go_ = (size_t)r_ * K + ck_ + c16_ * 8;                      \
        cp_async16(d_,          aH + go_);                                       \
        cp_async16(d_ + STG_AL, aL + go_);                                       \
        cp_async16(d_ + STG_BH, bH + go_);                                       \
        cp_async16(d_ + STG_BL, bL + go_);                                       \
    }                                                                            \
    cp_commit();                                                                 \
} while (0)

#define COMPUTE(ss) do {                                                         \
    const uint32_t bs_ = sb + (ss) * STG_SZ;                                     \
    _Pragma("unroll")                                                            \
    for (int ks = 0; ks < 4; ks++) {                                             \
        uint32_t ah[4][4], al[4][4], bh[4][2], bl[4][2];                         \
        _Pragma("unroll")                                                        \
        for (int mt = 0; mt < 4; mt++) {                                         \
            int r_ = wm * 64 + mt * 16 + lr + (g & 1) * 8;                       \
            int cA_ = ks * 2 + (g >> 1);                                         \
            uint32_t ad_ = bs_ + (uint32_t)(r_ * 128 + ((cA_ ^ (r_ & 7)) << 4)); \
            ldsm_x4(ah[mt][0], ah[mt][1], ah[mt][2], ah[mt][3], ad_);            \
            ldsm_x4(al[mt][0], al[mt][1], al[mt][2], al[mt][3], ad_ + STG_AL);   \
        }                                                                        \
        _Pragma("unroll")                                                        \
        for (int np = 0; np < 2; np++) {                                         \
            int n_ = wn * 32 + np * 16 + lr + (g >> 1) * 8;                      \
            int cB_ = ks * 2 + (g & 1);                                          \
            uint32_t bd_ = bs_ + STG_BH +                                        \
                           (uint32_t)(n_ * 128 + ((cB_ ^ (n_ & 7)) << 4));       \
            uint32_t t0, t1, t2, t3;                                             \
            ldsm_x4(t0, t1, t2, t3, bd_);                                        \
            bh[np * 2][0] = t0; bh[np * 2][1] = t1;                              \
            bh[np * 2 + 1][0] = t2; bh[np * 2 + 1][1] = t3;                      \
            ldsm_x4(t0, t1, t2, t3, bd_ + 16384);                                \
            bl[np * 2][0] = t0; bl[np * 2][1] = t1;                              \
            bl[np * 2 + 1][0] = t2; bl[np * 2 + 1][1] = t3;                      \
        }                                                                        \
        _Pragma("unroll")                                                        \
        for (int mt = 0; mt < 4; mt++)                                           \
            _Pragma("unroll")                                                    \
            for (int nt = 0; nt < 4; nt++) {                                     \
                mma_bf16(acc[mt][nt], ah[mt], bh[nt]);                           \
                mma_bf16(acc[mt][nt], ah[mt], bl[nt]);                           \
                mma_bf16(acc[mt][nt], al[mt], bh[nt]);                           \
            }                                                                    \
    }                                                                            \
} while (0)

    ISSUE(0, 0);
    for (int c = 0; c < NC; ++c) {
        const int st = c & 1;
        if (c + 1 < NC) {
            ISSUE(c + 1, st ^ 1);
            asm volatile("cp.async.wait_group 1;" ::: "memory");
        } else {
            asm volatile("cp.async.wait_group 0;" ::: "memory");
        }
        __syncthreads();
        COMPUTE(st);
        __syncthreads();
    }

    // epilogue
    const int rbase = m0 + wm * 64 + (lane >> 2);
    const int cbase = n0 + wn * 32 + (lane & 3) * 2;
    #pragma unroll
    for (int mt = 0; mt < 4; mt++) {
        #pragma unroll
        for (int nt = 0; nt < 4; nt++) {
            int row = rbase + mt * 16;
            int col = cbase + nt * 8;
            float bx = 0.f, by = 0.f;
            if (bias) { bx = bias[col]; by = bias[col + 1]; }
            float2 v0 = make_float2(acc[mt][nt][0] + bx, acc[mt][nt][1] + by);
            float2 v1 = make_float2(acc[mt][nt][2] + bx, acc[mt][nt][3] + by);
            *(float2*)(Cb + (size_t)row * ldc + col)       = v0;
            *(float2*)(Cb + (size_t)(row + 8) * ldc + col) = v1;
        }
    }
#undef ISSUE
#undef COMPUTE
}

// ---------------------------------------------------------------------------
// x fp32 -> hi/lo bf16 split
// ---------------------------------------------------------------------------
__global__ void cvt_x_kernel(const float4* __restrict__ x,
                             uint2* __restrict__ xhi, uint2* __restrict__ xlo)
{
    size_t i = (size_t)blockIdx.x * 256 + threadIdx.x;
    float4 v = x[i];
    __nv_bfloat16 h0 = __float2bfloat16(v.x);
    __nv_bfloat16 h1 = __float2bfloat16(v.y);
    __nv_bfloat16 h2 = __float2bfloat16(v.z);
    __nv_bfloat16 h3 = __float2bfloat16(v.w);
    __nv_bfloat16 l0 = __float2bfloat16(v.x - __bfloat162float(h0));
    __nv_bfloat16 l1 = __float2bfloat16(v.y - __bfloat162float(h1));
    __nv_bfloat16 l2 = __float2bfloat16(v.z - __bfloat162float(h2));
    __nv_bfloat16 l3 = __float2bfloat16(v.w - __bfloat162float(h3));
    uint2 hv, lv;
    hv.x = ((uint32_t)__bfloat16_as_ushort(h1) << 16) | __bfloat16_as_ushort(h0);
    hv.y = ((uint32_t)__bfloat16_as_ushort(h3) << 16) | __bfloat16_as_ushort(h2);
    lv.x = ((uint32_t)__bfloat16_as_ushort(l1) << 16) | __bfloat16_as_ushort(l0);
    lv.y = ((uint32_t)__bfloat16_as_ushort(l3) << 16) | __bfloat16_as_ushort(l2);
    xhi[i] = hv;
    xlo[i] = lv;
}

// ---------------------------------------------------------------------------
// pack Wq|Wk|Wv [1024][512] -> W^T hi/lo bf16 [1536][1024]
// ---------------------------------------------------------------------------
__global__ void pack_w_kernel(const float* __restrict__ Wq, const float* __restrict__ Wk,
                              const float* __restrict__ Wv,
                              __nv_bfloat16* __restrict__ wthi, __nv_bfloat16* __restrict__ wtlo)
{
    __shared__ float t[32][33];
    const float* W = (blockIdx.z == 0) ? Wq : (blockIdx.z == 1) ? Wk : Wv;
    int k = blockIdx.x * 32 + threadIdx.y;
    int c = blockIdx.y * 32 + threadIdx.x;
    t[threadIdx.y][threadIdx.x] = W[(size_t)k * 512 + c];
    __syncthreads();
    int n  = blockIdx.z * 512 + blockIdx.y * 32 + threadIdx.y;
    int kk = blockIdx.x * 32 + threadIdx.x;
    float v = t[threadIdx.x][threadIdx.y];
    __nv_bfloat16 h = __float2bfloat16(v);
    __nv_bfloat16 l = __float2bfloat16(v - __bfloat162float(h));
    wthi[(size_t)n * 1024 + kk] = h;
    wtlo[(size_t)n * 1024 + kk] = l;
}

// ---------------------------------------------------------------------------
// q softmax over 64-groups * QSCALE; reads C[.,0:512) (ld 1536), writes bf16 split.
// ---------------------------------------------------------------------------
__global__ void q_softmax2_kernel(const float* __restrict__ C,
                                  uint32_t* __restrict__ qhi, uint32_t* __restrict__ qlo)
{
    int w    = threadIdx.x >> 5;
    int lane = threadIdx.x & 31;
    size_t row = blockIdx.x;
    const float2 v = *(const float2*)(C + row * NTOT + w * 64 + lane * 2);
    float m = fmaxf(v.x, v.y);
    #pragma unroll
    for (int o = 16; o > 0; o >>= 1) m = fmaxf(m, __shfl_xor_sync(0xffffffffu, m, o));
    float ex = __expf(v.x - m), ey = __expf(v.y - m);
    float s = ex + ey;
    #pragma unroll
    for (int o = 16; o > 0; o >>= 1) s += __shfl_xor_sync(0xffffffffu, s, o);
    float sc = QSCALE / s;
    float a = ex * sc, b = ey * sc;
    __nv_bfloat16 ha = __float2bfloat16(a), hb = __float2bfloat16(b);
    __nv_bfloat16 la = __float2bfloat16(a - __bfloat162float(ha));
    __nv_bfloat16 lb = __float2bfloat16(b - __bfloat162float(hb));
    size_t o = row * 256 + w * 32 + lane;
    qhi[o] = ((uint32_t)__bfloat16_as_ushort(hb) << 16) | __bfloat16_as_ushort(ha);
    qlo[o] = ((uint32_t)__bfloat16_as_ushort(lb) << 16) | __bfloat16_as_ushort(la);
}

// ---------------------------------------------------------------------------
// k column stats (k lives in C cols [512,1024), ld 1536)
// ---------------------------------------------------------------------------
__global__ void k_stats_kernel(const float* __restrict__ C,
                               float* __restrict__ km, float* __restrict__ ksi)
{
    int b  = blockIdx.y;
    int c  = blockIdx.x * 64 + threadIdx.x;
    int ty = threadIdx.y;
    const float* base = C + (size_t)b * SEQ * NTOT + 512 + c;

    __shared__ float red[4][64];
    float m = -1e30f;
    for (int n = ty; n < SEQ; n += 4) m = fmaxf(m, base[(size_t)n * NTOT]);
    red[ty][threadIdx.x] = m;
    __syncthreads();
    m = fmaxf(fmaxf(red[0][threadIdx.x], red[1][threadIdx.x]),
              fmaxf(red[2][threadIdx.x], red[3][threadIdx.x]));
    __syncthreads();
    float s = 0.f;
    for (int n = ty; n < SEQ; n += 4) s += __expf(base[(size_t)n * NTOT] - m);
    red[ty][threadIdx.x] = s;
    __syncthreads();
    if (ty == 0) {
        float st = red[0][threadIdx.x] + red[1][threadIdx.x] +
                   red[2][threadIdx.x] + red[3][threadIdx.x];
        km [b * HID + c] = m;
        ksi[b * HID + c] = 1.0f / st;
    }
}

// ---------------------------------------------------------------------------
// partial context over 512-token chunks (k,v from C buffer, ld 1536)
// ---------------------------------------------------------------------------
__global__ __launch_bounds__(256, 4)
void context_kernel(const float* __restrict__ C,
                    const float* __restrict__ km, const float* __restrict__ ksi,
                    float* __restrict__ ctxp)
{
    int chunk = blockIdx.x, h = blockIdx.y, b = blockIdx.z;
    int tx = threadIdx.x, ty = threadIdx.y;
    int tid = ty * 16 + tx;

    __shared__ float Ks[32][64];
    __shared__ float Vs[32][64];
    __shared__ float ms[64], si[64];

    if (tid < 64) {
        ms[tid] = km [b * HID + h * DH + tid];
        si[tid] = ksi[b * HID + h * DH + tid];
    }
    __syncthreads();

    const float* kb = C + (size_t)b * SEQ * NTOT + 512  + h * DH;
    const float* vb = C + (size_t)b * SEQ * NTOT + 1024 + h * DH;
    int n0 = chunk * 512;

    float acc[4][4];
    #pragma unroll
    for (int r = 0; r < 4; r++)
        #pragma unroll
        for (int c = 0; c < 4; c++) acc[r][c] = 0.f;

    for (int nn = 0; nn < 512; nn += 32) {
        int ii = tid >> 3;
        int d0 = (tid & 7) * 8;
        size_t off = (size_t)(n0 + nn + ii) * NTOT + d0;
        float4 k0v = *(const float4*)(kb + off);
        float4 k1v = *(const float4*)(kb + off + 4);
        float4 v0v = *(const float4*)(vb + off);
        float4 v1v = *(const float4*)(vb + off + 4);
        Ks[ii][d0 + 0] = __expf(k0v.x - ms[d0 + 0]) * si[d0 + 0];
        Ks[ii][d0 + 1] = __expf(k0v.y - ms[d0 + 1]) * si[d0 + 1];
        Ks[ii][d0 + 2] = __expf(k0v.z - ms[d0 + 2]) * si[d0 + 2];
        Ks[ii][d0 + 3] = __expf(k0v.w - ms[d0 + 3]) * si[d0 + 3];
        Ks[ii][d0 + 4] = __expf(k1v.x - ms[d0 + 4]) * si[d0 + 4];
        Ks[ii][d0 + 5] = __expf(k1v.y - ms[d0 + 5]) * si[d0 + 5];
        Ks[ii][d0 + 6] = __expf(k1v.z - ms[d0 + 6]) * si[d0 + 6];
        Ks[ii][d0 + 7] = __expf(k1v.w - ms[d0 + 7]) * si[d0 + 7];
        *(float4*)(&Vs[ii][d0])     = v0v;
        *(float4*)(&Vs[ii][d0 + 4]) = v1v;
        __syncthreads();

        #pragma unroll
        for (int i = 0; i < 32; i++) {
            float4 rav = *(float4*)(&Ks[i][ty * 4]);
            float4 rbv = *(float4*)(&Vs[i][tx * 4]);
            float ra[4] = {rav.x, rav.y, rav.z, rav.w};
            float rb[4] = {rbv.x, rbv.y, rbv.z, rbv.w};
            #pragma unroll
            for (int r = 0; r < 4; r++)
                #pragma unroll
                for (int c = 0; c < 4; c++)
                    acc[r][c] += ra[r] * rb[c];
        }
        __syncthreads();
    }

    float* dst = ctxp + ((((size_t)chunk * BATCH + b) * HEADS + h) * DH) * DH;
    #pragma unroll
    for (int r = 0; r < 4; r++)
        #pragma unroll
        for (int c = 0; c < 4; c++)
            dst[(ty * 4 + r) * DH + tx * 4 + c] = acc[r][c];
}

// ---------------------------------------------------------------------------
// W2^T[b][j][k] = sum_e ctx[b][h][d][e]*Wo[h*64+e][j]  (k = h*64+d), bf16 split
// ---------------------------------------------------------------------------
__global__ void w2t_kernel(const float* __restrict__ ctxp, const float* __restrict__ Wo,
                           __nv_bfloat16* __restrict__ w2thi, __nv_bfloat16* __restrict__ w2tlo)
{
    int jt = blockIdx.x, h = blockIdx.y, b = blockIdx.z;
    int tx = threadIdx.x, ty = threadIdx.y;
    int tid = ty * 16 + tx;

    __shared__ float Cs[64][65];   // [d][e]
    __shared__ float Ws[64][64];   // [e][j]

    for (int l = tid; l < 4096; l += 256) {
        size_t base = ((size_t)b * HEADS + h) * 4096 + l;
        float s = 0.f;
        #pragma unroll
        for (int ch = 0; ch < 8; ch++)
            s += ctxp[base + (size_t)ch * (BATCH * HEADS * 4096)];
        Cs[l >> 6][l & 63] = s;
    }
    for (int l = tid; l < 4096; l += 256) {
        int e = l >> 6, jj = l & 63;
        Ws[e][jj] = Wo[(size_t)(h * DH + e) * QD + jt * 64 + jj];
    }
    __syncthreads();

    float acc[4][4];
    #pragma unroll
    for (int a = 0; a < 4; a++)
        #pragma unroll
        for (int d = 0; d < 4; d++) acc[a][d] = 0.f;

    #pragma unroll
    for (int e = 0; e < 64; e++) {
        float wv[4], cv[4];
        #pragma unroll
        for (int a = 0; a < 4; a++) wv[a] = Ws[e][ty * 4 + a];
        #pragma unroll
        for (int d = 0; d < 4; d++) cv[d] = Cs[tx * 4 + d][e];
        #pragma unroll
        for (int a = 0; a < 4; a++)
            #pragma unroll
            for (int d = 0; d < 4; d++)
                acc[a][d] += wv[a] * cv[d];
    }

    #pragma unroll
    for (int a = 0; a < 4; a++) {
        int j = jt * 64 + ty * 4 + a;
        #pragma unroll
        for (int d = 0; d < 4; d++) {
            int kc = h * DH + tx * 4 + d;
            float v = acc[a][d];
            __nv_bfloat16 hh = __float2bfloat16(v);
            __nv_bfloat16 ll = __float2bfloat16(v - __bfloat162float(hh));
            size_t o = ((size_t)b * QD + j) * HID + kc;
            w2thi[o] = hh;
            w2tlo[o] = ll;
        }
    }
}

// ---------------------------------------------------------------------------
extern "C" void kernel_launch(void* const* d_in, const int* in_sizes, int n_in,
                              void* d_out, int out_size)
{
    const float* x  = (const float*)d_in[0];
    const float* Wq = (const float*)d_in[1];
    const float* Wk = (const float*)d_in[2];
    const float* Wv = (const float*)d_in[3];
    const float* Wo = (const float*)d_in[4];
    const float* bo = (const float*)d_in[5];
    float* out = (float*)d_out;

    unsigned char* sc = nullptr;
    cudaGetSymbolAddress((void**)&sc, g_scratch);

    float*         Cbuf = (float*)        (sc + SC_C);
    __nv_bfloat16* xhi  = (__nv_bfloat16*)(sc + SC_XHI);
    __nv_bfloat16* xlo  = (__nv_bfloat16*)(sc + SC_XLO);
    __nv_bfloat16* wthi = (__nv_bfloat16*)(sc + SC_WTHI);
    __nv_bfloat16* wtlo = (__nv_bfloat16*)(sc + SC_WTLO);
    __nv_bfloat16* qhi  = (__nv_bfloat16*)(sc + SC_QHI);
    __nv_bfloat16* qlo  = (__nv_bfloat16*)(sc + SC_QLO);
    float*         km   = (float*)        (sc + SC_KM);
    float*         ksi  = (float*)        (sc + SC_KSI);
    float*         ctxp = (float*)        (sc + SC_CTXP);
    __nv_bfloat16* w2hi = (__nv_bfloat16*)(sc + SC_W2THI);
    __nv_bfloat16* w2lo = (__nv_bfloat16*)(sc + SC_W2TLO);

    cudaFuncSetAttribute(gemm_mma, cudaFuncAttributeMaxDynamicSharedMemorySize, GSM_TOTAL);

    // 1) splits
    cvt_x_kernel<<<MROWS * QD / (256 * 4), 256>>>((const float4*)x, (uint2*)xhi, (uint2*)xlo);
    pack_w_kernel<<<dim3(32, 16, 3), dim3(32, 32)>>>(Wq, Wk, Wv, wthi, wtlo);

    // 2) QKV fused GEMM: [16384,1024] x [1024,1536] -> Cbuf [16384][1536]
    gemm_mma<<<dim3(NTOT / 128, MROWS / 128, 1), 256, GSM_TOTAL>>>(
        xhi, xlo, wthi, wtlo, Cbuf, nullptr, QD, NTOT, 0, 0, 0);

    // 3) q softmax -> bf16 split
    q_softmax2_kernel<<<MROWS, 256>>>(Cbuf, (uint32_t*)qhi, (uint32_t*)qlo);

    // 4) k stats
    k_stats_kernel<<<dim3(HID / 64, BATCH), dim3(64, 4)>>>(Cbuf, km, ksi);

    // 5) partial context
    context_kernel<<<dim3(8, HEADS, BATCH), dim3(16, 16)>>>(Cbuf, km, ksi, ctxp);

    // 6) W2^T build (bf16 split)
    w2t_kernel<<<dim3(16, HEADS, BATCH), dim3(16, 16)>>>(ctxp, Wo, w2hi, w2lo);

    // 7) final batched GEMM: out[b] = q_soft[b] @ W2[b] + bo
    gemm_mma<<<dim3(QD / 128, SEQ / 128, BATCH), 256, GSM_TOTAL>>>(
        qhi, qlo, w2hi, w2lo, out, bo, HID, QD,
        (long long)SEQ * HID, (long long)QD * HID, (long long)SEQ * QD);
}

// round 5
// speedup vs baseline: 2.9325x; 1.2180x over previous
#include <cuda_runtime.h>
#include <cuda_fp16.h>
#include <cstdint>

// ---------------- problem constants ----------------
#define BATCH 4
#define SEQ   4096
#define QD    1024
#define HEADS 8
#define DH    64
#define HID   512
#define MROWS (BATCH*SEQ)     // 16384
#define NTOT  1536            // q|k|v packed columns
#define QSCALE 0.125f

// ---------------- scratch layout (bytes) ----------------
#define SC_C      0ull                    // qkv fp32 [16384][1536]
#define SC_XH     100663296ull           // x fp16 [16384][1024]
#define SC_WTHI   134217728ull           // W^T hi fp16 [1536][1024]
#define SC_WTLO   137363456ull
#define SC_QH     140509184ull           // q_soft fp16 [16384][512]
#define SC_KM     157286400ull           // [4][512] fp32
#define SC_KSI    157294592ull
#define SC_CTXP   157302784ull           // [8][4][8][64][64] fp32
#define SC_W2THI  161497088ull           // W2^T hi fp16 [4][1024][512]
#define SC_W2TLO  165691392ull
#define SC_TOTAL  169885696ull

__device__ __align__(1024) unsigned char g_scratch[SC_TOTAL];

// ---------------- PTX helpers ----------------
__device__ __forceinline__ uint32_t smem_u32(const void* p) {
    uint32_t a;
    asm("{ .reg .u64 t; cvta.to.shared.u64 t, %1; cvt.u32.u64 %0, t; }" : "=r"(a) : "l"(p));
    return a;
}
__device__ __forceinline__ void cp_async16(uint32_t dst, const void* src) {
    asm volatile("cp.async.cg.shared.global [%0], [%1], 16;" :: "r"(dst), "l"(src) : "memory");
}
__device__ __forceinline__ void cp_commit() {
    asm volatile("cp.async.commit_group;" ::: "memory");
}
__device__ __forceinline__ void ldsm_x4(uint32_t& r0, uint32_t& r1, uint32_t& r2, uint32_t& r3,
                                        uint32_t addr) {
    asm volatile("ldmatrix.sync.aligned.m8n8.x4.shared.b16 {%0,%1,%2,%3}, [%4];"
                 : "=r"(r0), "=r"(r1), "=r"(r2), "=r"(r3) : "r"(addr));
}
__device__ __forceinline__ void mma_f16(float* d, const uint32_t* a, const uint32_t* b) {
    asm volatile(
        "mma.sync.aligned.m16n8k16.row.col.f32.f16.f16.f32 "
        "{%0,%1,%2,%3}, {%4,%5,%6,%7}, {%8,%9}, {%0,%1,%2,%3};"
        : "+f"(d[0]), "+f"(d[1]), "+f"(d[2]), "+f"(d[3])
        : "r"(a[0]), "r"(a[1]), "r"(a[2]), "r"(a[3]), "r"(b[0]), "r"(b[1]));
}

// smem stage: A 16KB | BH 32KB | BL 32KB = 80KB per stage, 2 stages
#define STG_BH 16384
#define STG_BL 49152
#define STG_SZ 81920
#define GSM_TOTAL (2*STG_SZ)   // 163840

// ---------------------------------------------------------------------------
// fp16 2-term split GEMM via mma.sync:
//   C[m][n] = sum_k A[m][k]*(Bh[n][k]+Bl[n][k]) (+bias[n])
// CTA tile 128(M) x 256(N), BK=64, 256 threads (8 warps 2x4; warp = 64x64).
// grid: (N/256, M/128, batch)
// ---------------------------------------------------------------------------
__global__ __launch_bounds__(256, 1)
void gemm_mma(const __half* __restrict__ A,
              const __half* __restrict__ Bhi, const __half* __restrict__ Blo,
              float* __restrict__ C, const float* __restrict__ bias,
              int K, int ldc,
              long long sA, long long sB, long long sC)
{
    extern __shared__ char smem[];
    const uint32_t sb = smem_u32(smem);
    const int tid  = threadIdx.x;
    const int wid  = tid >> 5;
    const int lane = tid & 31;
    const int wm = wid >> 2;           // 0..1
    const int wn = wid & 3;            // 0..3

    const int n0 = blockIdx.x * 256;
    const int m0 = blockIdx.y * 128;
    const long long bz = blockIdx.z;
    const __half* aP = A   + bz * sA + (size_t)m0 * K;
    const __half* bH = Bhi + bz * sB + (size_t)n0 * K;
    const __half* bL = Blo + bz * sB + (size_t)n0 * K;
    float* Cb = C + bz * sC;

    const int NC = K >> 6;

    float acc[4][8][4];
    #pragma unroll
    for (int i = 0; i < 4; i++)
        #pragma unroll
        for (int j = 0; j < 8; j++)
            #pragma unroll
            for (int l = 0; l < 4; l++) acc[i][j][l] = 0.f;

    const int g  = lane >> 3;     // ldmatrix address group 0..3
    const int lr = lane & 7;

#define ISSUE(cc, ss) do {                                                       \
    const int ck_ = (cc) << 6;                                                   \
    const uint32_t bs_ = sb + (ss) * STG_SZ;                                     \
    _Pragma("unroll")                                                            \
    for (int j_ = 0; j_ < 4; j_++) {                                             \
        int idx_ = tid + j_ * 256;                                               \
        int r_ = idx_ >> 3, c16_ = idx_ & 7;                                     \
        uint32_t d_ = bs_ + (uint32_t)(r_ * 128 + ((c16_ ^ (r_ & 7)) << 4));     \
        cp_async16(d_, aP + (size_t)r_ * K + ck_ + c16_ * 8);                    \
    }                                                                            \
    _Pragma("unroll")                                                            \
    for (int j_ = 0; j_ < 8; j_++) {                                             \
        int idx_ = tid + j_ * 256;                                               \
        int r_ = idx_ >> 3, c16_ = idx_ & 7;                                     \
        uint32_t d_ = bs_ + (uint32_t)(r_ * 128 + ((c16_ ^ (r_ & 7)) << 4));     \
        const size_t go_ = (size_t)r_ * K + ck_ + c16_ * 8;                      \
        cp_async16(d_ + STG_BH, bH + go_);                                       \
        cp_async16(d_ + STG_BL, bL + go_);                                       \
    }                                                                            \
    cp_commit();                                                                 \
} while (0)

#define COMPUTE(ss) do {                                                         \
    const uint32_t bs_ = sb + (ss) * STG_SZ;                                     \
    _Pragma("unroll")                                                            \
    for (int ks = 0; ks < 4; ks++) {                                             \
        uint32_t ah[4][4];                                                       \
        _Pragma("unroll")                                                        \
        for (int mt = 0; mt < 4; mt++) {                                         \
            int r_ = wm * 64 + mt * 16 + lr + (g & 1) * 8;                       \
            int cA_ = ks * 2 + (g >> 1);                                         \
            uint32_t ad_ = bs_ + (uint32_t)(r_ * 128 + ((cA_ ^ (r_ & 7)) << 4)); \
            ldsm_x4(ah[mt][0], ah[mt][1], ah[mt][2], ah[mt][3], ad_);            \
        }                                                                        \
        _Pragma("unroll")                                                        \
        for (int np = 0; np < 4; np++) {                                         \
            int n_ = wn * 64 + np * 16 + lr + (g >> 1) * 8;                      \
            int cB_ = ks * 2 + (g & 1);                                          \
            uint32_t boff_ = (uint32_t)(n_ * 128 + ((cB_ ^ (n_ & 7)) << 4));     \
            uint32_t bh[2][2], bl[2][2], t0, t1, t2, t3;                         \
            ldsm_x4(t0, t1, t2, t3, bs_ + STG_BH + boff_);                       \
            bh[0][0] = t0; bh[0][1] = t1; bh[1][0] = t2; bh[1][1] = t3;          \
            ldsm_x4(t0, t1, t2, t3, bs_ + STG_BL + boff_);                       \
            bl[0][0] = t0; bl[0][1] = t1; bl[1][0] = t2; bl[1][1] = t3;          \
            _Pragma("unroll")                                                    \
            for (int mt = 0; mt < 4; mt++) {                                     \
                mma_f16(acc[mt][np * 2],     ah[mt], bh[0]);                     \
                mma_f16(acc[mt][np * 2 + 1], ah[mt], bh[1]);                     \
                mma_f16(acc[mt][np * 2],     ah[mt], bl[0]);                     \
                mma_f16(acc[mt][np * 2 + 1], ah[mt], bl[1]);                     \
            }                                                                    \
        }                                                                        \
    }                                                                            \
} while (0)

    ISSUE(0, 0);
    for (int c = 0; c < NC; ++c) {
        const int st = c & 1;
        if (c + 1 < NC) {
            ISSUE(c + 1, st ^ 1);
            asm volatile("cp.async.wait_group 1;" ::: "memory");
        } else {
            asm volatile("cp.async.wait_group 0;" ::: "memory");
        }
        __syncthreads();
        COMPUTE(st);
        __syncthreads();
    }

    // epilogue: warp tile 64x64
    const int rbase = m0 + wm * 64 + (lane >> 2);
    const int cbase = n0 + wn * 64 + (lane & 3) * 2;
    #pragma unroll
    for (int mt = 0; mt < 4; mt++) {
        #pragma unroll
        for (int nt = 0; nt < 8; nt++) {
            int row = rbase + mt * 16;
            int col = cbase + nt * 8;
            float bx = 0.f, by = 0.f;
            if (bias) { bx = bias[col]; by = bias[col + 1]; }
            float2 v0 = make_float2(acc[mt][nt][0] + bx, acc[mt][nt][1] + by);
            float2 v1 = make_float2(acc[mt][nt][2] + bx, acc[mt][nt][3] + by);
            *(float2*)(Cb + (size_t)row * ldc + col)       = v0;
            *(float2*)(Cb + (size_t)(row + 8) * ldc + col) = v1;
        }
    }
#undef ISSUE
#undef COMPUTE
}

// ---------------------------------------------------------------------------
// x fp32 -> fp16 (single)
// ---------------------------------------------------------------------------
__global__ void cvt_x_kernel(const float4* __restrict__ x, uint2* __restrict__ xh)
{
    size_t i = (size_t)blockIdx.x * 256 + threadIdx.x;
    float4 v = x[i];
    uint2 hv;
    __half2 p0 = __floats2half2_rn(v.x, v.y);
    __half2 p1 = __floats2half2_rn(v.z, v.w);
    hv.x = *(uint32_t*)&p0;
    hv.y = *(uint32_t*)&p1;
    xh[i] = hv;
}

// ---------------------------------------------------------------------------
// pack Wq|Wk|Wv [1024][512] -> W^T hi/lo fp16 [1536][1024]
// ---------------------------------------------------------------------------
__global__ void pack_w_kernel(const float* __restrict__ Wq, const float* __restrict__ Wk,
                              const float* __restrict__ Wv,
                              __half* __restrict__ wthi, __half* __restrict__ wtlo)
{
    __shared__ float t[32][33];
    const float* W = (blockIdx.z == 0) ? Wq : (blockIdx.z == 1) ? Wk : Wv;
    int k = blockIdx.x * 32 + threadIdx.y;
    int c = blockIdx.y * 32 + threadIdx.x;
    t[threadIdx.y][threadIdx.x] = W[(size_t)k * 512 + c];
    __syncthreads();
    int n  = blockIdx.z * 512 + blockIdx.y * 32 + threadIdx.y;
    int kk = blockIdx.x * 32 + threadIdx.x;
    float v = t[threadIdx.x][threadIdx.y];
    __half h = __float2half_rn(v);
    __half l = __float2half_rn(v - __half2float(h));
    wthi[(size_t)n * 1024 + kk] = h;
    wtlo[(size_t)n * 1024 + kk] = l;
}

// ---------------------------------------------------------------------------
// q softmax over 64-groups * QSCALE; reads C[.,0:512) (ld 1536), writes fp16.
// ---------------------------------------------------------------------------
__global__ void q_softmax2_kernel(const float* __restrict__ C, uint32_t* __restrict__ qh)
{
    int w    = threadIdx.x >> 5;
    int lane = threadIdx.x & 31;
    size_t row = blockIdx.x;
    const float2 v = *(const float2*)(C + row * NTOT + w * 64 + lane * 2);
    float m = fmaxf(v.x, v.y);
    #pragma unroll
    for (int o = 16; o > 0; o >>= 1) m = fmaxf(m, __shfl_xor_sync(0xffffffffu, m, o));
    float ex = __expf(v.x - m), ey = __expf(v.y - m);
    float s = ex + ey;
    #pragma unroll
    for (int o = 16; o > 0; o >>= 1) s += __shfl_xor_sync(0xffffffffu, s, o);
    float sc = QSCALE / s;
    __half2 p = __floats2half2_rn(ex * sc, ey * sc);
    qh[row * 256 + w * 32 + lane] = *(uint32_t*)&p;
}

// ---------------------------------------------------------------------------
// k column stats (k lives in C cols [512,1024), ld 1536)
// ---------------------------------------------------------------------------
__global__ void k_stats_kernel(const float* __restrict__ C,
                               float* __restrict__ km, float* __restrict__ ksi)
{
    int b  = blockIdx.y;
    int c  = blockIdx.x * 64 + threadIdx.x;
    int ty = threadIdx.y;
    const float* base = C + (size_t)b * SEQ * NTOT + 512 + c;

    __shared__ float red[4][64];
    float m = -1e30f;
    for (int n = ty; n < SEQ; n += 4) m = fmaxf(m, base[(size_t)n * NTOT]);
    red[ty][threadIdx.x] = m;
    __syncthreads();
    m = fmaxf(fmaxf(red[0][threadIdx.x], red[1][threadIdx.x]),
              fmaxf(red[2][threadIdx.x], red[3][threadIdx.x]));
    __syncthreads();
    float s = 0.f;
    for (int n = ty; n < SEQ; n += 4) s += __expf(base[(size_t)n * NTOT] - m);
    red[ty][threadIdx.x] = s;
    __syncthreads();
    if (ty == 0) {
        float st = red[0][threadIdx.x] + red[1][threadIdx.x] +
                   red[2][threadIdx.x] + red[3][threadIdx.x];
        km [b * HID + c] = m;
        ksi[b * HID + c] = 1.0f / st;
    }
}

// ---------------------------------------------------------------------------
// partial context over 512-token chunks (k,v from C buffer, ld 1536)
// ---------------------------------------------------------------------------
__global__ __launch_bounds__(256, 4)
void context_kernel(const float* __restrict__ C,
                    const float* __restrict__ km, const float* __restrict__ ksi,
                    float* __restrict__ ctxp)
{
    int chunk = blockIdx.x, h = blockIdx.y, b = blockIdx.z;
    int tx = threadIdx.x, ty = threadIdx.y;
    int tid = ty * 16 + tx;

    __shared__ float Ks[32][64];
    __shared__ float Vs[32][64];
    __shared__ float ms[64], si[64];

    if (tid < 64) {
        ms[tid] = km [b * HID + h * DH + tid];
        si[tid] = ksi[b * HID + h * DH + tid];
    }
    __syncthreads();

    const float* kb = C + (size_t)b * SEQ * NTOT + 512  + h * DH;
    const float* vb = C + (size_t)b * SEQ * NTOT + 1024 + h * DH;
    int n0 = chunk * 512;

    float acc[4][4];
    #pragma unroll
    for (int r = 0; r < 4; r++)
        #pragma unroll
        for (int c = 0; c < 4; c++) acc[r][c] = 0.f;

    for (int nn = 0; nn < 512; nn += 32) {
        int ii = tid >> 3;
        int d0 = (tid & 7) * 8;
        size_t off = (size_t)(n0 + nn + ii) * NTOT + d0;
        float4 k0v = *(const float4*)(kb + off);
        float4 k1v = *(const float4*)(kb + off + 4);
        float4 v0v = *(const float4*)(vb + off);
        float4 v1v = *(const float4*)(vb + off + 4);
        Ks[ii][d0 + 0] = __expf(k0v.x - ms[d0 + 0]) * si[d0 + 0];
        Ks[ii][d0 + 1] = __expf(k0v.y - ms[d0 + 1]) * si[d0 + 1];
        Ks[ii][d0 + 2] = __expf(k0v.z - ms[d0 + 2]) * si[d0 + 2];
        Ks[ii][d0 + 3] = __expf(k0v.w - ms[d0 + 3]) * si[d0 + 3];
        Ks[ii][d0 + 4] = __expf(k1v.x - ms[d0 + 4]) * si[d0 + 4];
        Ks[ii][d0 + 5] = __expf(k1v.y - ms[d0 + 5]) * si[d0 + 5];
        Ks[ii][d0 + 6] = __expf(k1v.z - ms[d0 + 6]) * si[d0 + 6];
        Ks[ii][d0 + 7] = __expf(k1v.w - ms[d0 + 7]) * si[d0 + 7];
        *(float4*)(&Vs[ii][d0])     = v0v;
        *(float4*)(&Vs[ii][d0 + 4]) = v1v;
        __syncthreads();

        #pragma unroll
        for (int i = 0; i < 32; i++) {
            float4 rav = *(float4*)(&Ks[i][ty * 4]);
            float4 rbv = *(float4*)(&Vs[i][tx * 4]);
            float ra[4] = {rav.x, rav.y, rav.z, rav.w};
            float rb[4] = {rbv.x, rbv.y, rbv.z, rbv.w};
            #pragma unroll
            for (int r = 0; r < 4; r++)
                #pragma unroll
                for (int c = 0; c < 4; c++)
                    acc[r][c] += ra[r] * rb[c];
        }
        __syncthreads();
    }

    float* dst = ctxp + ((((size_t)chunk * BATCH + b) * HEADS + h) * DH) * DH;
    #pragma unroll
    for (int r = 0; r < 4; r++)
        #pragma unroll
        for (int c = 0; c < 4; c++)
            dst[(ty * 4 + r) * DH + tx * 4 + c] = acc[r][c];
}

// ---------------------------------------------------------------------------
// W2^T[b][j][k] = sum_e ctx[b][h][d][e]*Wo[h*64+e][j]  (k = h*64+d), fp16 split
// ---------------------------------------------------------------------------
__global__ void w2t_kernel(const float* __restrict__ ctxp, const float* __restrict__ Wo,
                           __half* __restrict__ w2thi, __half* __restrict__ w2tlo)
{
    int jt = blockIdx.x, h = blockIdx.y, b = blockIdx.z;
    int tx = threadIdx.x, ty = threadIdx.y;
    int tid = ty * 16 + tx;

    __shared__ float Cs[64][65];   // [d][e]
    __shared__ float Ws[64][64];   // [e][j]

    for (int l = tid; l < 4096; l += 256) {
        size_t base = ((size_t)b * HEADS + h) * 4096 + l;
        float s = 0.f;
        #pragma unroll
        for (int ch = 0; ch < 8; ch++)
            s += ctxp[base + (size_t)ch * (BATCH * HEADS * 4096)];
        Cs[l >> 6][l & 63] = s;
    }
    for (int l = tid; l < 4096; l += 256) {
        int e = l >> 6, jj = l & 63;
        Ws[e][jj] = Wo[(size_t)(h * DH + e) * QD + jt * 64 + jj];
    }
    __syncthreads();

    float acc[4][4];
    #pragma unroll
    for (int a = 0; a < 4; a++)
        #pragma unroll
        for (int d = 0; d < 4; d++) acc[a][d] = 0.f;

    #pragma unroll
    for (int e = 0; e < 64; e++) {
        float wv[4], cv[4];
        #pragma unroll
        for (int a = 0; a < 4; a++) wv[a] = Ws[e][ty * 4 + a];
        #pragma unroll
        for (int d = 0; d < 4; d++) cv[d] = Cs[tx * 4 + d][e];
        #pragma unroll
        for (int a = 0; a < 4; a++)
            #pragma unroll
            for (int d = 0; d < 4; d++)
                acc[a][d] += wv[a] * cv[d];
    }

    #pragma unroll
    for (int a = 0; a < 4; a++) {
        int j = jt * 64 + ty * 4 + a;
        #pragma unroll
        for (int d = 0; d < 4; d++) {
            int kc = h * DH + tx * 4 + d;
            float v = acc[a][d];
            __half hh = __float2half_rn(v);
            __half ll = __float2half_rn(v - __half2float(hh));
            size_t o = ((size_t)b * QD + j) * HID + kc;
            w2thi[o] = hh;
            w2tlo[o] = ll;
        }
    }
}

// ---------------------------------------------------------------------------
extern "C" void kernel_launch(void* const* d_in, const int* in_sizes, int n_in,
                              void* d_out, int out_size)
{
    const float* x  = (const float*)d_in[0];
    const float* Wq = (const float*)d_in[1];
    const float* Wk = (const float*)d_in[2];
    const float* Wv = (const float*)d_in[3];
    const float* Wo = (const float*)d_in[4];
    const float* bo = (const float*)d_in[5];
    float* out = (float*)d_out;

    unsigned char* sc = nullptr;
    cudaGetSymbolAddress((void**)&sc, g_scratch);

    float*   Cbuf = (float*)  (sc + SC_C);
    __half*  xh   = (__half*) (sc + SC_XH);
    __half*  wthi = (__half*) (sc + SC_WTHI);
    __half*  wtlo = (__half*) (sc + SC_WTLO);
    __half*  qh   = (__half*) (sc + SC_QH);
    float*   km   = (float*)  (sc + SC_KM);
    float*   ksi  = (float*)  (sc + SC_KSI);
    float*   ctxp = (float*)  (sc + SC_CTXP);
    __half*  w2hi = (__half*) (sc + SC_W2THI);
    __half*  w2lo = (__half*) (sc + SC_W2TLO);

    cudaFuncSetAttribute(gemm_mma, cudaFuncAttributeMaxDynamicSharedMemorySize, GSM_TOTAL);

    // 1) conversions
    cvt_x_kernel<<<MROWS * QD / (256 * 4), 256>>>((const float4*)x, (uint2*)xh);
    pack_w_kernel<<<dim3(32, 16, 3), dim3(32, 32)>>>(Wq, Wk, Wv, wthi, wtlo);

    // 2) QKV fused GEMM: [16384,1024] x [1024,1536] -> Cbuf [16384][1536]
    gemm_mma<<<dim3(NTOT / 256, MROWS / 128, 1), 256, GSM_TOTAL>>>(
        xh, wthi, wtlo, Cbuf, nullptr, QD, NTOT, 0, 0, 0);

    // 3) q softmax -> fp16
    q_softmax2_kernel<<<MROWS, 256>>>(Cbuf, (uint32_t*)qh);

    // 4) k stats
    k_stats_kernel<<<dim3(HID / 64, BATCH), dim3(64, 4)>>>(Cbuf, km, ksi);

    // 5) partial context
    context_kernel<<<dim3(8, HEADS, BATCH), dim3(16, 16)>>>(Cbuf, km, ksi, ctxp);

    // 6) W2^T build (fp16 split)
    w2t_kernel<<<dim3(16, HEADS, BATCH), dim3(16, 16)>>>(ctxp, Wo, w2hi, w2lo);

    // 7) final batched GEMM: out[b] = q_soft[b] @ W2[b] + bo
    gemm_mma<<<dim3(QD / 256, SEQ / 128, BATCH), 256, GSM_TOTAL>>>(
        qh, w2hi, w2lo, out, bo, HID, QD,
        (long long)SEQ * HID, (long long)QD * HID, (long long)SEQ * QD);
}